// round 11
// baseline (speedup 1.0000x reference)
#include <cuda_runtime.h>
#include <cuda_bf16.h>
#include <math.h>
#include <stdint.h>

#define BB   2
#define TT   16
#define NN   2048
#define CI1  32
#define CHH  64
#define EE   32768
#define T1   14
#define T2   12
#define F1   (BB*T1*CHH)
#define F14  (F1/4)
#define NB_TOTAL (NN*BB)

__device__ __forceinline__ uint32_t pkbf2(float a, float b) {
    __nv_bfloat162 h = __floats2bfloat162_rn(a, b);
    return *reinterpret_cast<uint32_t*>(&h);
}
__device__ __forceinline__ void mma_bf16(float* d, const uint32_t* a,
                                         uint32_t b0, uint32_t b1) {
    asm volatile(
        "mma.sync.aligned.m16n8k16.row.col.f32.bf16.bf16.f32 "
        "{%0,%1,%2,%3}, {%4,%5,%6,%7}, {%8,%9}, {%0,%1,%2,%3};"
        : "+f"(d[0]), "+f"(d[1]), "+f"(d[2]), "+f"(d[3])
        : "r"(a[0]), "r"(a[1]), "r"(a[2]), "r"(a[3]), "r"(b0), "r"(b1));
}
__device__ __forceinline__ void ldsm4(uint32_t* r, uint32_t a) {
    asm volatile("ldmatrix.sync.aligned.m8n8.x4.shared.b16 {%0,%1,%2,%3}, [%4];"
        : "=r"(r[0]), "=r"(r[1]), "=r"(r[2]), "=r"(r[3]) : "r"(a));
}
__device__ __forceinline__ uint32_t s2u(const void* p) {
    uint32_t a;
    asm("{ .reg .u64 t; cvta.to.shared.u64 t, %1; cvt.u32.u64 %0, t; }"
        : "=r"(a) : "l"(p));
    return a;
}

// ---------------- scratch ----------------------------------------------------
__device__ __align__(16) float g_t1 [NB_TOTAL*T1*CHH];
__device__ __align__(16) float g_tx1[NB_TOTAL*T1*CHH];
__device__ __align__(16) float g_tx2[NB_TOTAL*T1*CHH];
__device__ __align__(16) float g_t2 [NB_TOTAL*T1*CHH];
__device__ __align__(16) float g_t3 [NB_TOTAL*T2*CHH];
__device__ int   g_rowstart[NN+1];
__device__ int   g_ccol[EE];
__device__ float g_cnorm[EE];
// tconv2 prepped weights: [3 kc][192 n][64 k]
__device__ __align__(16) __nv_bfloat16 g_bh[3*192*64];
__device__ __align__(16) __nv_bfloat16 g_bl[3*192*64];
// tconv1 prepped weights: [192 n][96 k]
__device__ __align__(16) __nv_bfloat16 g_b1h[192*96];
__device__ __align__(16) __nv_bfloat16 g_b1l[192*96];
// cheb prepped weights: [3 j][64 n][64 k]
__device__ __align__(16) __nv_bfloat16 g_chh[3*64*64];
__device__ __align__(16) __nv_bfloat16 g_chl[3*64*64];

// ---------------- fused graph preprocessing (single block) -------------------
__global__ void __launch_bounds__(1024) k_graphprep(const int* __restrict__ ei,
                                                    const float* __restrict__ ew) {
    __shared__ float sdeg[NN];   // deg, then dis
    __shared__ int   scnt[NN];   // count, then cursor
    __shared__ int   srow[NN];   // rowstart[0..NN-1]
    __shared__ int   ws[32];
    int tid = threadIdx.x;
    for (int i = tid; i < NN; i += 1024) { sdeg[i] = 0.f; scnt[i] = 0; }
    __syncthreads();
    for (int e = tid; e < EE; e += 1024) {
        int r = ei[e], c = ei[EE + e];
        float w = (r == c) ? 0.f : ew[e];
        atomicAdd(&sdeg[r], w);
        atomicAdd(&scnt[r], 1);
    }
    __syncthreads();
    // dis (overwrite sdeg)
    for (int i = tid; i < NN; i += 1024) {
        float d = sdeg[i];
        sdeg[i] = (d > 0.f) ? rsqrtf(d) : 0.f;
    }
    // scan of scnt (2 per thread)
    int v0 = scnt[2 * tid], v1 = scnt[2 * tid + 1];
    int s = v0 + v1;
    int lane = tid & 31, wid = tid >> 5;
    int sc = s;
#pragma unroll
    for (int o = 1; o < 32; o <<= 1) {
        int t = __shfl_up_sync(0xffffffffu, sc, o);
        if (lane >= o) sc += t;
    }
    if (lane == 31) ws[wid] = sc;
    __syncthreads();
    if (wid == 0) {
        int w = ws[lane];
#pragma unroll
        for (int o = 1; o < 32; o <<= 1) {
            int t = __shfl_up_sync(0xffffffffu, w, o);
            if (lane >= o) w += t;
        }
        ws[lane] = w;
    }
    __syncthreads();
    int base = ((wid > 0) ? ws[wid - 1] : 0) + sc - s;
    // rowstart: [2tid+1] = base+v0, [2tid+2] = base+v0+v1, [0]=0
    int rs1 = base + v0, rs2 = base + v0 + v1;
    g_rowstart[2 * tid + 1] = rs1;
    g_rowstart[2 * tid + 2] = rs2;
    srow[2 * tid + 1] = rs1;
    if (2 * tid + 2 < NN) srow[2 * tid + 2] = rs2;
    if (tid == 0) { g_rowstart[0] = 0; srow[0] = 0; }
    __syncthreads();
    // reuse scnt as cursor
    for (int i = tid; i < NN; i += 1024) scnt[i] = 0;
    __syncthreads();
    for (int e = tid; e < EE; e += 1024) {
        int r = ei[e], c = ei[EE + e];
        float w = (r == c) ? 0.f : ew[e];
        int pos = srow[r] + atomicAdd(&scnt[r], 1);
        g_ccol[pos]  = c;
        g_cnorm[pos] = -sdeg[r] * w * sdeg[c];
    }
}

// ---------------- weight prep: fp32 -> bf16 hi/lo ----------------------------
__global__ void k_wprep(const float* __restrict__ w1, const float* __restrict__ w2,
                        const float* __restrict__ w3,
                        const float* __restrict__ v1, const float* __restrict__ v2,
                        const float* __restrict__ v3,
                        const float* __restrict__ cw) {
    int idx = blockIdx.x * blockDim.x + threadIdx.x;
    if (idx < 3 * 192 * 64) {                       // tconv2
        int kc = idx / (192 * 64);
        int n  = (idx / 64) % 192;
        int ci = idx % 64;
        int j  = n / 64, co = n % 64;
        const float* wj = (j == 0) ? w1 : ((j == 1) ? w2 : w3);
        float v = wj[(co * 64 + ci) * 3 + kc];
        __nv_bfloat16 h = __float2bfloat16(v);
        g_bh[idx] = h;
        g_bl[idx] = __float2bfloat16(v - __bfloat162float(h));
    }
    int idx1 = idx - 3 * 192 * 64;                  // tconv1
    if (idx1 >= 0 && idx1 < 192 * 96) {
        int n  = idx1 / 96;
        int k  = idx1 % 96;
        int tap = k >> 5, ci = k & 31;
        int j  = n / 64, co = n % 64;
        const float* wj = (j == 0) ? v1 : ((j == 1) ? v2 : v3);
        float v = wj[(co * 32 + ci) * 3 + tap];
        __nv_bfloat16 h = __float2bfloat16(v);
        g_b1h[idx1] = h;
        g_b1l[idx1] = __float2bfloat16(v - __bfloat162float(h));
    }
    int idx2 = idx1 - 192 * 96;                     // cheb
    if (idx2 >= 0 && idx2 < 3 * 64 * 64) {
        int j  = idx2 / (64 * 64);
        int n  = (idx2 / 64) % 64;
        int k  = idx2 % 64;
        float v = cw[(j * 64 + k) * 64 + n];
        __nv_bfloat16 h = __float2bfloat16(v);
        g_chh[idx2] = h;
        g_chl[idx2] = __float2bfloat16(v - __bfloat162float(h));
    }
}

// =============================================================================
// tconv1 HMMA: M=57344 (nb,t14), N=192, K=96; 16 warps x (M16 x N96); ldmatrix.
// =============================================================================
#define AP1 104
#define BP1 104
#define O1_AH   768
#define O1_AL   (O1_AH + 128*AP1*2)
#define O1_BH   (O1_AL + 128*AP1*2)
#define O1_BL   (O1_BH + 192*BP1*2)
#define SMEM_H1 (O1_BL + 192*BP1*2)   /* 133888 */

__global__ void __launch_bounds__(512, 1) k_tconv1_hmma(
    const float* __restrict__ x,
    const float* __restrict__ bb1, const float* __restrict__ bb2,
    const float* __restrict__ bb3)
{
    extern __shared__ char smem[];
    float*         sbias = (float*)smem;
    __nv_bfloat16* sAh   = (__nv_bfloat16*)(smem + O1_AH);
    __nv_bfloat16* sAl   = (__nv_bfloat16*)(smem + O1_AL);
    __nv_bfloat16* sBh   = (__nv_bfloat16*)(smem + O1_BH);
    __nv_bfloat16* sBl   = (__nv_bfloat16*)(smem + O1_BL);

    int tid = threadIdx.x;
    if (tid < 64) {
        sbias[tid]       = bb1[tid];
        sbias[64 + tid]  = bb2[tid];
        sbias[128 + tid] = bb3[tid];
    }

    // ---- stage A: 128 rows x 96 k; 4 threads/row
    {
        int rA = tid >> 2, quarter = tid & 3;
        long R = (long)blockIdx.x * 128 + rA;
        int nb = (int)(R / 14), t = (int)(R % 14);
        int b = nb & 1, n = nb >> 1;
        const float* xb = x + (long)b * (TT * NN * CI1) + (long)n * CI1;
#pragma unroll
        for (int k4 = 0; k4 < 6; k4++) {
            int k = quarter * 24 + k4 * 4;
            int tap = k >> 5, ci = k & 31;
            float4 v = __ldg((const float4*)(xb + (long)(t + tap) * (NN * CI1) + ci));
            float hx = __bfloat162float(__float2bfloat16(v.x));
            float hy = __bfloat162float(__float2bfloat16(v.y));
            float hz = __bfloat162float(__float2bfloat16(v.z));
            float hw = __bfloat162float(__float2bfloat16(v.w));
            uint32_t off = (uint32_t)rA * (AP1 * 2) + k * 2;
            *(uint2*)((char*)sAh + off) = make_uint2(pkbf2(hx, hy), pkbf2(hz, hw));
            *(uint2*)((char*)sAl + off) = make_uint2(pkbf2(v.x - hx, v.y - hy),
                                                     pkbf2(v.z - hz, v.w - hw));
        }
    }
    // ---- stage B
    for (int u = tid; u < 192 * 12; u += 512) {
        int nn2 = u / 12, c16 = u % 12;
        uint32_t dst = (uint32_t)nn2 * (BP1 * 2) + c16 * 16;
        *(uint4*)((char*)sBh + dst) = *(const uint4*)((const char*)g_b1h + nn2 * 192 + c16 * 16);
        *(uint4*)((char*)sBl + dst) = *(const uint4*)((const char*)g_b1l + nn2 * 192 + c16 * 16);
    }
    __syncthreads();

    int lane = tid & 31, w = tid >> 5;
    int m0 = (w >> 1) * 16;
    int c0 = (w & 1) * 32;
    int g  = lane >> 2, tg = lane & 3;
    int lane7 = lane & 7;

    uint32_t aRow  = m0 + lane7 + ((lane >> 3) & 1) * 8;
    uint32_t aBH = s2u(sAh) + aRow * (AP1 * 2) + (lane >> 4) * 16;
    uint32_t aBL = s2u(sAl) + aRow * (AP1 * 2) + (lane >> 4) * 16;
    uint32_t bRow  = lane7 + (lane >> 4) * 8;
    uint32_t bKoff = ((lane >> 3) & 1) * 16;
    uint32_t bBH = s2u(sBh) + (bRow + c0) * (BP1 * 2) + bKoff;
    uint32_t bBL = s2u(sBl) + (bRow + c0) * (BP1 * 2) + bKoff;

    float acc[12][4];
#pragma unroll
    for (int nt = 0; nt < 12; nt++)
#pragma unroll
        for (int q = 0; q < 4; q++) acc[nt][q] = 0.f;

#pragma unroll
    for (int ks = 0; ks < 6; ks++) {
        uint32_t ah[4], al[4];
        ldsm4(ah, aBH + ks * 32);
        ldsm4(al, aBL + ks * 32);
#pragma unroll
        for (int p2 = 0; p2 < 6; p2++) {
            uint32_t noff = ((p2 >> 1) * 64 + (p2 & 1) * 16) * (BP1 * 2);
            uint32_t bh[4], bl[4];
            ldsm4(bh, bBH + noff + ks * 32);
            ldsm4(bl, bBL + noff + ks * 32);
            int nt = 2 * p2;
            mma_bf16(acc[nt],     ah, bh[0], bh[1]);
            mma_bf16(acc[nt],     ah, bl[0], bl[1]);
            mma_bf16(acc[nt],     al, bh[0], bh[1]);
            mma_bf16(acc[nt + 1], ah, bh[2], bh[3]);
            mma_bf16(acc[nt + 1], ah, bl[2], bl[3]);
            mma_bf16(acc[nt + 1], al, bh[2], bh[3]);
        }
    }

    // ---- in-register gating epilogue (acc index nt = 4*gate + cb)
#pragma unroll
    for (int rs = 0; rs < 2; rs++) {
        int row = m0 + g + rs * 8;
        long R = (long)blockIdx.x * 128 + row;
        int nb = (int)(R / 14), t = (int)(R % 14);
        float* orow = g_t1 + ((long)nb * T1 + t) * 64;
#pragma unroll
        for (int cb = 0; cb < 4; cb++) {
            // acc[2*p2+q] with p2 = gate*2 + (cb>>1), q = cb&1 == acc[4*gate+cb]? No:
            // pair p2 covers cb = 2*(p2&1)+q  -> acc index = 2*p2+q = 4*(p2>>1)+2*(p2&1)*2? 
            // mapping: gate=p2>>1, cb=2*(p2&1)+q, idx=2*p2+q = 4*gate + 2*(p2&1)*... 
            // For gate fixed: p2&1=cb>>1, q=cb&1 => idx = 4*gate + 2*(cb>>1) + (cb&1)
            int i0 = 2 * (cb >> 1) + (cb & 1);
            int col = c0 + cb * 8 + 2 * tg;
#pragma unroll
            for (int qq = 0; qq < 2; qq++) {
                float a1 = acc[i0][rs * 2 + qq]     + sbias[col + qq];
                float a2 = acc[4 + i0][rs * 2 + qq] + sbias[64 + col + qq];
                float a3 = acc[8 + i0][rs * 2 + qq] + sbias[128 + col + qq];
                float sg = __fdividef(1.f, 1.f + __expf(-a2));
                float v  = a1 + sg + a3;
                orow[col + qq] = (v > 0.f) ? v : 0.f;
            }
        }
    }
}

// =============================================================================
// tconv2 HMMA: M=49152 (nb,t12), N=192, K=3 kc x 64; ldmatrix.
// =============================================================================
#define AP2 72
#define BP2 72
#define O2_AH   768
#define O2_AL   (O2_AH + 128*AP2*2)
#define O2_BH   (O2_AL + 128*AP2*2)
#define O2_BL   (O2_BH + 192*BP2*2)
#define SMEM_H2 (O2_BL + 192*BP2*2)   /* 92928 */

__global__ void __launch_bounds__(512, 1) k_tconv2_hmma(
    const float* __restrict__ bb1, const float* __restrict__ bb2,
    const float* __restrict__ bb3)
{
    extern __shared__ char smem[];
    float*         sbias = (float*)smem;
    __nv_bfloat16* sAh   = (__nv_bfloat16*)(smem + O2_AH);
    __nv_bfloat16* sAl   = (__nv_bfloat16*)(smem + O2_AL);
    __nv_bfloat16* sBh   = (__nv_bfloat16*)(smem + O2_BH);
    __nv_bfloat16* sBl   = (__nv_bfloat16*)(smem + O2_BL);

    int tid = threadIdx.x;
    if (tid < 64) {
        sbias[tid]       = bb1[tid];
        sbias[64 + tid]  = bb2[tid];
        sbias[128 + tid] = bb3[tid];
    }

    int lane = tid & 31, w = tid >> 5;
    int m0 = (w >> 1) * 16;
    int c0 = (w & 1) * 32;
    int g  = lane >> 2, tg = lane & 3;
    int lane7 = lane & 7;

    uint32_t aRow  = m0 + lane7 + ((lane >> 3) & 1) * 8;
    uint32_t aBH = s2u(sAh) + aRow * (AP2 * 2) + (lane >> 4) * 16;
    uint32_t aBL = s2u(sAl) + aRow * (AP2 * 2) + (lane >> 4) * 16;
    uint32_t bRow  = lane7 + (lane >> 4) * 8;
    uint32_t bKoff = ((lane >> 3) & 1) * 16;
    uint32_t bBH = s2u(sBh) + (bRow + c0) * (BP2 * 2) + bKoff;
    uint32_t bBL = s2u(sBl) + (bRow + c0) * (BP2 * 2) + bKoff;

    int rA = tid >> 2, quarter = tid & 3;
    long RA = (long)blockIdx.x * 128 + rA;
    int nbA = (int)(RA / 12), tA = (int)(RA % 12);

    float acc[12][4];
#pragma unroll
    for (int nt = 0; nt < 12; nt++)
#pragma unroll
        for (int q = 0; q < 4; q++) acc[nt][q] = 0.f;

    for (int kc = 0; kc < 3; kc++) {
        __syncthreads();
        // ---- stage A
        {
            const float4* src = (const float4*)(g_t2 + ((long)nbA * T1 + tA + kc) * 64)
                                + quarter * 4;
            uint32_t off = (uint32_t)rA * (AP2 * 2) + quarter * 32;
            uint2* dh = (uint2*)((char*)sAh + off);
            uint2* dl = (uint2*)((char*)sAl + off);
#pragma unroll
            for (int v4 = 0; v4 < 4; v4++) {
                float4 xv = __ldg(&src[v4]);
                float hx = __bfloat162float(__float2bfloat16(xv.x));
                float hy = __bfloat162float(__float2bfloat16(xv.y));
                float hz = __bfloat162float(__float2bfloat16(xv.z));
                float hw = __bfloat162float(__float2bfloat16(xv.w));
                dh[v4] = make_uint2(pkbf2(hx, hy), pkbf2(hz, hw));
                dl[v4] = make_uint2(pkbf2(xv.x - hx, xv.y - hy),
                                    pkbf2(xv.z - hz, xv.w - hw));
            }
        }
        // ---- stage B for this kc
        {
            const char* bh = (const char*)(g_bh + (long)kc * 192 * 64);
            const char* bl = (const char*)(g_bl + (long)kc * 192 * 64);
            for (int u = tid; u < 192 * 8; u += 512) {
                int nn2 = u >> 3, c16 = u & 7;
                uint32_t dst = (uint32_t)nn2 * (BP2 * 2) + c16 * 16;
                *(uint4*)((char*)sBh + dst) = *(const uint4*)(bh + nn2 * 128 + c16 * 16);
                *(uint4*)((char*)sBl + dst) = *(const uint4*)(bl + nn2 * 128 + c16 * 16);
            }
        }
        __syncthreads();

#pragma unroll
        for (int ks = 0; ks < 4; ks++) {
            uint32_t ah[4], al[4];
            ldsm4(ah, aBH + ks * 32);
            ldsm4(al, aBL + ks * 32);
#pragma unroll
            for (int p2 = 0; p2 < 6; p2++) {
                uint32_t noff = ((p2 >> 1) * 64 + (p2 & 1) * 16) * (BP2 * 2);
                uint32_t bh[4], bl[4];
                ldsm4(bh, bBH + noff + ks * 32);
                ldsm4(bl, bBL + noff + ks * 32);
                int nt = 2 * p2;
                mma_bf16(acc[nt],     ah, bh[0], bh[1]);
                mma_bf16(acc[nt],     ah, bl[0], bl[1]);
                mma_bf16(acc[nt],     al, bh[0], bh[1]);
                mma_bf16(acc[nt + 1], ah, bh[2], bh[3]);
                mma_bf16(acc[nt + 1], ah, bl[2], bl[3]);
                mma_bf16(acc[nt + 1], al, bh[2], bh[3]);
            }
        }
    }

#pragma unroll
    for (int rs = 0; rs < 2; rs++) {
        int row = m0 + g + rs * 8;
        long R = (long)blockIdx.x * 128 + row;
        int nb = (int)(R / 12), t = (int)(R % 12);
        float* orow = g_t3 + ((long)nb * T2 + t) * 64;
#pragma unroll
        for (int cb = 0; cb < 4; cb++) {
            int i0 = 2 * (cb >> 1) + (cb & 1);
            int col = c0 + cb * 8 + 2 * tg;
#pragma unroll
            for (int qq = 0; qq < 2; qq++) {
                float a1 = acc[i0][rs * 2 + qq]     + sbias[col + qq];
                float a2 = acc[4 + i0][rs * 2 + qq] + sbias[64 + col + qq];
                float a3 = acc[8 + i0][rs * 2 + qq] + sbias[128 + col + qq];
                float sg = __fdividef(1.f, 1.f + __expf(-a2));
                float v  = a1 + sg + a3;
                orow[col + qq] = (v > 0.f) ? v : 0.f;
            }
        }
    }
}

// =============================================================================
// cheb HMMA: M=57344 rows, N=64, K=3 j x 64; 16 warps x (M16 x N64); ldmatrix.
// =============================================================================
#define APC 72
#define BPC 72
#define OC_AH   256
#define OC_AL   (OC_AH + 256*APC*2)
#define OC_BH   (OC_AL + 256*APC*2)
#define OC_BL   (OC_BH + 64*BPC*2)
#define SMEM_HC (OC_BL + 64*BPC*2)    /* 92416 */

__global__ void __launch_bounds__(512, 1) k_cheb_hmma(const float* __restrict__ bias)
{
    extern __shared__ char smem[];
    float*         sbias = (float*)smem;
    __nv_bfloat16* sAh   = (__nv_bfloat16*)(smem + OC_AH);
    __nv_bfloat16* sAl   = (__nv_bfloat16*)(smem + OC_AL);
    __nv_bfloat16* sBh   = (__nv_bfloat16*)(smem + OC_BH);
    __nv_bfloat16* sBl   = (__nv_bfloat16*)(smem + OC_BL);

    int tid = threadIdx.x;
    if (tid < 64) sbias[tid] = bias[tid];

    int lane = tid & 31, w = tid >> 5;
    int m0 = w * 16;
    int g  = lane >> 2, tg = lane & 3;
    int lane7 = lane & 7;

    uint32_t aRow  = m0 + lane7 + ((lane >> 3) & 1) * 8;
    uint32_t aBH = s2u(sAh) + aRow * (APC * 2) + (lane >> 4) * 16;
    uint32_t aBL = s2u(sAl) + aRow * (APC * 2) + (lane >> 4) * 16;
    uint32_t bRow  = lane7 + (lane >> 4) * 8;
    uint32_t bKoff = ((lane >> 3) & 1) * 16;
    uint32_t bBH = s2u(sBh) + bRow * (BPC * 2) + bKoff;
    uint32_t bBL = s2u(sBl) + bRow * (BPC * 2) + bKoff;

    int rA = tid >> 1, half = tid & 1;
    long RA = (long)blockIdx.x * 256 + rA;

    float acc[8][4];
#pragma unroll
    for (int nt = 0; nt < 8; nt++)
#pragma unroll
        for (int q = 0; q < 4; q++) acc[nt][q] = 0.f;

    for (int j = 0; j < 3; j++) {
        __syncthreads();
        // ---- stage A chunk: 256 rows x 64 k from Txj
        {
            const float* srcj = (j == 0) ? g_t1 : ((j == 1) ? g_tx1 : g_tx2);
            const float4* src = (const float4*)(srcj + RA * 64) + half * 8;
            uint32_t off = (uint32_t)rA * (APC * 2) + half * 64;
            uint2* dh = (uint2*)((char*)sAh + off);
            uint2* dl = (uint2*)((char*)sAl + off);
#pragma unroll
            for (int v4 = 0; v4 < 8; v4++) {
                float4 xv = __ldg(&src[v4]);
                float hx = __bfloat162float(__float2bfloat16(xv.x));
                float hy = __bfloat162float(__float2bfloat16(xv.y));
                float hz = __bfloat162float(__float2bfloat16(xv.z));
                float hw = __bfloat162float(__float2bfloat16(xv.w));
                dh[v4] = make_uint2(pkbf2(hx, hy), pkbf2(hz, hw));
                dl[v4] = make_uint2(pkbf2(xv.x - hx, xv.y - hy),
                                    pkbf2(xv.z - hz, xv.w - hw));
            }
        }
        // ---- stage B chunk: 64 x 64
        if (tid < 64 * 8) {
            int nn2 = tid >> 3, c16 = tid & 7;
            uint32_t dst = (uint32_t)nn2 * (BPC * 2) + c16 * 16;
            const char* bh = (const char*)(g_chh + (long)j * 64 * 64);
            const char* bl = (const char*)(g_chl + (long)j * 64 * 64);
            *(uint4*)((char*)sBh + dst) = *(const uint4*)(bh + nn2 * 128 + c16 * 16);
            *(uint4*)((char*)sBl + dst) = *(const uint4*)(bl + nn2 * 128 + c16 * 16);
        }
        __syncthreads();

#pragma unroll
        for (int ks = 0; ks < 4; ks++) {
            uint32_t ah[4], al[4];
            ldsm4(ah, aBH + ks * 32);
            ldsm4(al, aBL + ks * 32);
#pragma unroll
            for (int p2 = 0; p2 < 4; p2++) {
                uint32_t noff = (uint32_t)(p2 * 16) * (BPC * 2);
                uint32_t bh[4], bl[4];
                ldsm4(bh, bBH + noff + ks * 32);
                ldsm4(bl, bBL + noff + ks * 32);
                int nt = 2 * p2;
                mma_bf16(acc[nt],     ah, bh[0], bh[1]);
                mma_bf16(acc[nt],     ah, bl[0], bl[1]);
                mma_bf16(acc[nt],     al, bh[0], bh[1]);
                mma_bf16(acc[nt + 1], ah, bh[2], bh[3]);
                mma_bf16(acc[nt + 1], ah, bl[2], bl[3]);
                mma_bf16(acc[nt + 1], al, bh[2], bh[3]);
            }
        }
    }

    // ---- bias + relu epilogue (acc[nt] covers cols nt*8..nt*8+7)
#pragma unroll
    for (int rs = 0; rs < 2; rs++) {
        int row = m0 + g + rs * 8;
        long R = (long)blockIdx.x * 256 + row;
        float* orow = g_t2 + R * 64;
#pragma unroll
        for (int nt = 0; nt < 8; nt++) {
            int col = nt * 8 + 2 * tg;
            float v0 = acc[nt][rs * 2 + 0] + sbias[col];
            float v1 = acc[nt][rs * 2 + 1] + sbias[col + 1];
            v0 = (v0 > 0.f) ? v0 : 0.f;
            v1 = (v1 > 0.f) ? v1 : 0.f;
            *(float2*)(orow + col) = make_float2(v0, v1);
        }
    }
}

// ---------------- ChebConv propagation (CSR gather) --------------------------
__global__ void k_prop(const float4* __restrict__ z, float4* __restrict__ out,
                       const float4* __restrict__ x0, int mode)
{
    int n = blockIdx.x;
    int tid = threadIdx.x;
    int e0 = g_rowstart[n], e1 = g_rowstart[n + 1];
    float4 acc = make_float4(0.f, 0.f, 0.f, 0.f);
    for (int e = e0; e < e1; e++) {
        int   c  = __ldg(&g_ccol[e]);
        float nm = __ldg(&g_cnorm[e]);
        float4 v = __ldg(&z[(long)c * F14 + tid]);
        acc.x += nm * v.x; acc.y += nm * v.y;
        acc.z += nm * v.z; acc.w += nm * v.w;
    }
    if (mode) {
        float4 v0 = __ldg(&x0[(long)n * F14 + tid]);
        acc.x = 2.f * acc.x - v0.x; acc.y = 2.f * acc.y - v0.y;
        acc.z = 2.f * acc.z - v0.z; acc.w = 2.f * acc.w - v0.w;
    }
    out[(long)n * F14 + tid] = acc;
}

// ---------------- BN (channel axis = node) + final transpose -----------------
__global__ void k_bn(const float* __restrict__ gamma, const float* __restrict__ beta,
                     float* __restrict__ out)
{
    int n = blockIdx.x;
    const float* tp = g_t3 + (long)n * (BB * T2 * 64);
    float s = 0.f, s2 = 0.f;
    for (int i = threadIdx.x; i < BB * T2 * 64; i += 256) {
        float v = tp[i]; s += v; s2 += v * v;
    }
    __shared__ float rs[8], rs2[8];
    for (int o = 16; o; o >>= 1) {
        s  += __shfl_down_sync(0xffffffff, s,  o);
        s2 += __shfl_down_sync(0xffffffff, s2, o);
    }
    int lane = threadIdx.x & 31, wid = threadIdx.x >> 5;
    if (lane == 0) { rs[wid] = s; rs2[wid] = s2; }
    __syncthreads();
    __shared__ float smu, srstd;
    if (wid == 0) {
        float a  = (lane < 8) ? rs[lane]  : 0.f;
        float a2 = (lane < 8) ? rs2[lane] : 0.f;
        for (int o = 4; o; o >>= 1) {
            a  += __shfl_down_sync(0xffffffff, a,  o);
            a2 += __shfl_down_sync(0xffffffff, a2, o);
        }
        if (lane == 0) {
            float mu  = a / 1536.f;
            float var = a2 / 1536.f - mu * mu;
            smu = mu; srstd = rsqrtf(var + 1e-5f);
        }
    }
    __syncthreads();
    float mu = smu, rstd = srstd;
    float ga = gamma[n], be = beta[n];
    for (int i = threadIdx.x; i < BB * T2 * 64; i += 256) {
        float v = (tp[i] - mu) * rstd * ga + be;
        int c = i & 63;
        int t = (i >> 6) % T2;
        int b = i / (T2 * 64);
        out[(((long)b * T2 + t) * NN + n) * 64 + c] = v;
    }
}

// ---------------- launch -----------------------------------------------------
extern "C" void kernel_launch(void* const* d_in, const int* in_sizes, int n_in,
                              void* d_out, int out_size)
{
    const float* X    = (const float*)d_in[0];
    const int*   ei   = (const int*)  d_in[1];
    const float* ew   = (const float*)d_in[2];
    const float* t1w1 = (const float*)d_in[3];
    const float* t1b1 = (const float*)d_in[4];
    const float* t1w2 = (const float*)d_in[5];
    const float* t1b2 = (const float*)d_in[6];
    const float* t1w3 = (const float*)d_in[7];
    const float* t1b3 = (const float*)d_in[8];
    const float* chw  = (const float*)d_in[9];
    const float* chb  = (const float*)d_in[10];
    const float* t2w1 = (const float*)d_in[11];
    const float* t2b1 = (const float*)d_in[12];
    const float* t2w2 = (const float*)d_in[13];
    const float* t2b2 = (const float*)d_in[14];
    const float* t2w3 = (const float*)d_in[15];
    const float* t2b3 = (const float*)d_in[16];
    const float* gam  = (const float*)d_in[17];
    const float* bet  = (const float*)d_in[18];
    float* out = (float*)d_out;

    void *p_t1, *p_tx1, *p_tx2;
    cudaGetSymbolAddress(&p_t1,  g_t1);
    cudaGetSymbolAddress(&p_tx1, g_tx1);
    cudaGetSymbolAddress(&p_tx2, g_tx2);

    cudaFuncSetAttribute(k_tconv1_hmma, cudaFuncAttributeMaxDynamicSharedMemorySize, SMEM_H1);
    cudaFuncSetAttribute(k_tconv2_hmma, cudaFuncAttributeMaxDynamicSharedMemorySize, SMEM_H2);
    cudaFuncSetAttribute(k_cheb_hmma,   cudaFuncAttributeMaxDynamicSharedMemorySize, SMEM_HC);

    const int NPREP = 3*192*64 + 192*96 + 3*64*64;

    k_wprep<<<(NPREP + 255) / 256, 256>>>(                           // 0
        t2w1, t2w2, t2w3, t1w1, t1w2, t1w3, chw);

    k_tconv1_hmma<<<NB_TOTAL * T1 / 128, 512, SMEM_H1>>>(X, t1b1, t1b2, t1b3);  // 1

    k_graphprep<<<1, 1024>>>(ei, ew);                                // 2

    // 3 (profiled slot): prop
    k_prop<<<NN, F14>>>((const float4*)p_t1,  (float4*)p_tx1, (const float4*)p_t1, 0);
    k_prop<<<NN, F14>>>((const float4*)p_tx1, (float4*)p_tx2, (const float4*)p_t1, 1);

    k_cheb_hmma<<<NB_TOTAL * T1 / 256, 512, SMEM_HC>>>(chb);

    k_tconv2_hmma<<<NB_TOTAL * T2 / 128, 512, SMEM_H2>>>(t2b1, t2b2, t2b3);

    k_bn<<<NN, 256>>>(gam, bet, out);
}